// round 13
// baseline (speedup 1.0000x reference)
#include <cuda_runtime.h>
#include <cuda_bf16.h>
#include <cstdint>
#include <math.h>

// Problem constants
#define BDIM 8
#define SDIM 1024
#define HDIM 768
#define NH   12
#define HD   64
#define MROWS (BDIM*SDIM)        // 8192
#define NROWSEL (BDIM*NH*SDIM)   // 98304 rows (b,h,q)
#define NCOL 48                  // 24 q-logit cols | 24 k-logit cols
#define KP   2304                // split-K: [hi|hi|lo] x [hi|lo|hi]
#define KCH  72                  // KP/32 k-chunks
#define TINYF 1.17549435e-38f

#define NCHUNK 4
#define ROWS_PER_CHUNK (NROWSEL/NCHUNK)   // 24576 scan rows
#define M_PER_CHUNK (MROWS/NCHUNK)        // 2048 m-rows

// Scratch (allocation-free rule: __device__ globals)
__device__ float d_V[MROWS * HDIM];             // V = x@Wv + bv (f32)
__device__ float d_Wc[HDIM * NCOL];             // folded logit weights
__device__ float d_bc[NCOL];
__device__ float d_L[MROWS * NCOL];             // logits [8192][48] (q|k)
__device__ unsigned char d_code[BDIM*NH*SDIM];
__device__ int d_kstar[BDIM*NH*SDIM];
// split-bf16 GEMM operands (K-folded 3-product layout)
__device__ __nv_bfloat16 d_Ap[MROWS * KP];      // x:  [Ah | Ah | Al]
__device__ __nv_bfloat16 d_Agp[MROWS * KP];     // gathered V, same layout
__device__ __nv_bfloat16 d_Bv[HDIM * KP];       // WvT: [Bh | Bl | Bh]
__device__ __nv_bfloat16 d_Bw[HDIM * KP];       // WpT: [Bh | Bl | Bh]

__device__ __forceinline__ uint32_t smem_u32(const void* p) {
  uint32_t a;
  asm("{ .reg .u64 t; cvta.to.shared.u64 t, %1; cvt.u32.u64 %0, t; }" : "=r"(a) : "l"(p));
  return a;
}

// ======================= JAX threefry2x32 =======================
__device__ __forceinline__ void threefry(unsigned k0, unsigned k1,
                                         unsigned &x0, unsigned &x1) {
  unsigned k2 = k0 ^ k1 ^ 0x1BD11BDAu;
  x0 += k0; x1 += k1;
#define TF_R(r) { x0 += x1; x1 = __funnelshift_l(x1, x1, r); x1 ^= x0; }
  TF_R(13) TF_R(15) TF_R(26) TF_R(6)
  x0 += k1; x1 += k2 + 1u;
  TF_R(17) TF_R(29) TF_R(16) TF_R(24)
  x0 += k2; x1 += k0 + 2u;
  TF_R(13) TF_R(15) TF_R(26) TF_R(6)
  x0 += k0; x1 += k1 + 3u;
  TF_R(17) TF_R(29) TF_R(16) TF_R(24)
  x0 += k1; x1 += k2 + 4u;
  TF_R(13) TF_R(15) TF_R(26) TF_R(6)
  x0 += k2; x1 += k0 + 5u;
#undef TF_R
}
__device__ __forceinline__ unsigned tf_bits(unsigned k0, unsigned k1, unsigned lo) {
  unsigned x0 = 0u, x1 = lo;
  threefry(k0, k1, x0, x1);
  return x0 ^ x1;
}
__device__ __forceinline__ float u_from_v23(unsigned v23) {
  float f = __uint_as_float(v23 | 0x3f800000u) - 1.0f;
  return fmaxf(f, TINYF);
}
__device__ __forceinline__ float gumbel_of_u(float u) {
  return (float)(-log(-log((double)u)));
}

// ============ split helper ============
__device__ __forceinline__ void split4(float4 v, uint2 &h, uint2 &l) {
  unsigned short hx = __bfloat16_as_ushort(__float2bfloat16(v.x));
  unsigned short hy = __bfloat16_as_ushort(__float2bfloat16(v.y));
  unsigned short hz = __bfloat16_as_ushort(__float2bfloat16(v.z));
  unsigned short hw = __bfloat16_as_ushort(__float2bfloat16(v.w));
  unsigned short lx = __bfloat16_as_ushort(__float2bfloat16(v.x - __bfloat162float(__ushort_as_bfloat16(hx))));
  unsigned short ly = __bfloat16_as_ushort(__float2bfloat16(v.y - __bfloat162float(__ushort_as_bfloat16(hy))));
  unsigned short lz = __bfloat16_as_ushort(__float2bfloat16(v.z - __bfloat162float(__ushort_as_bfloat16(hz))));
  unsigned short lw = __bfloat16_as_ushort(__float2bfloat16(v.w - __bfloat162float(__ushort_as_bfloat16(hw))));
  h = make_uint2((unsigned)hx | ((unsigned)hy << 16), (unsigned)hz | ((unsigned)hw << 16));
  l = make_uint2((unsigned)lx | ((unsigned)ly << 16), (unsigned)lz | ((unsigned)lw << 16));
}

// ============ prep_wc: fold Wc = [Wq@Cblk | Wk@Cblk], bc likewise ============
__global__ void prep_wc(const float* __restrict__ Wq, const float* __restrict__ Wk,
                        const float* __restrict__ bq, const float* __restrict__ bk,
                        const float* __restrict__ cent) {
  int t = blockIdx.x * blockDim.x + threadIdx.x;
  if (t < HDIM * NCOL) {
    int row = t / NCOL, j = t - row * NCOL;
    const float* W = (j < 24) ? Wq : Wk;
    int h = (j % 24) >> 1, c = j & 1;
    float s = 0.f;
#pragma unroll
    for (int d = 0; d < HD; d++)
      s += W[row * HDIM + h * HD + d] * cent[d * 2 + c];
    d_Wc[row * NCOL + j] = s;
  } else if (t < HDIM * NCOL + NCOL) {
    int j = t - HDIM * NCOL;
    const float* bb = (j < 24) ? bq : bk;
    int h = (j % 24) >> 1, c = j & 1;
    float s = 0.f;
#pragma unroll
    for (int d = 0; d < HD; d++)
      s += bb[h * HD + d] * cent[d * 2 + c];
    d_bc[j] = s;
  }
}

// ============ conv_all: x-split + both W-splits (runs on s2) ============
#define NB_X   6144
#define NB_W   2304
__global__ __launch_bounds__(256) void conv_all(
    const float* __restrict__ x,
    const float* __restrict__ Wv, const float* __restrict__ Wp)
{
  int tid = threadIdx.x;
  if (blockIdx.x < NB_X) {
    int i = blockIdx.x * 256 + tid;
    int row = i / 192, c4 = (i - row * 192) * 4;
    uint2 h, l;
    split4(((const float4*)x)[i], h, l);
    size_t base = (size_t)row * KP + c4;
    *(uint2*)(d_Ap + base)        = h;
    *(uint2*)(d_Ap + base + 768)  = h;
    *(uint2*)(d_Ap + base + 1536) = l;
  } else {
    int wi = blockIdx.x - NB_X;
    const float* W = (wi < NB_W) ? Wv : Wp;
    __nv_bfloat16* Bp = (wi < NB_W) ? d_Bv : d_Bw;
    int idx = (wi % NB_W) * 256 + tid;
    int n = idx / HDIM, k = idx - n * HDIM;
    float v = W[(size_t)k * HDIM + n];
    __nv_bfloat16 hb = __float2bfloat16(v);
    __nv_bfloat16 lb = __float2bfloat16(v - __bfloat162float(hb));
    size_t base = (size_t)n * KP;
    Bp[base + k]        = hb;
    Bp[base + 768 + k]  = lb;
    Bp[base + 1536 + k] = hb;
  }
}

// ============ logits_centroid: L = x@Wc+bc + fused centroid codes ============
__global__ __launch_bounds__(256) void logits_centroid(const float* __restrict__ x) {
  __shared__ float Xs[64][65];
  __shared__ float Ws[64][NCOL];
  int tid = threadIdx.x;
  int row0 = blockIdx.x * 64;
  int r = tid & 63, g = tid >> 6;
  float acc[12] = {};
  for (int k0 = 0; k0 < HDIM; k0 += 64) {
    __syncthreads();
#pragma unroll
    for (int i = 0; i < 4; i++) {
      int f4 = tid + i * 256;
      int fr = f4 >> 4, fc = (f4 & 15) * 4;
      float4 v = *(const float4*)(x + (size_t)(row0 + fr) * HDIM + k0 + fc);
      Xs[fr][fc+0] = v.x; Xs[fr][fc+1] = v.y; Xs[fr][fc+2] = v.z; Xs[fr][fc+3] = v.w;
    }
#pragma unroll
    for (int i = 0; i < 3; i++) {
      int f4 = tid + i * 256;
      int wr = f4 / 12, wc = (f4 % 12) * 4;
      *(float4*)&Ws[wr][wc] = *(const float4*)(d_Wc + (size_t)(k0 + wr) * NCOL + wc);
    }
    __syncthreads();
#pragma unroll 4
    for (int kk = 0; kk < 64; kk++) {
      float xv = Xs[r][kk];
      const float4* w4 = (const float4*)&Ws[kk][g * 12];
#pragma unroll
      for (int q4 = 0; q4 < 3; q4++) {
        float4 w = w4[q4];
        acc[q4*4+0] += xv * w.x;
        acc[q4*4+1] += xv * w.y;
        acc[q4*4+2] += xv * w.z;
        acc[q4*4+3] += xv * w.w;
      }
    }
  }
  float* Lp = d_L + (size_t)(row0 + r) * NCOL + g * 12;
#pragma unroll
  for (int q4 = 0; q4 < 3; q4++) {
    float4 o;
    o.x = acc[q4*4+0] + d_bc[g*12 + q4*4+0];
    o.y = acc[q4*4+1] + d_bc[g*12 + q4*4+1];
    o.z = acc[q4*4+2] + d_bc[g*12 + q4*4+2];
    o.w = acc[q4*4+3] + d_bc[g*12 + q4*4+3];
    *(float4*)(Lp + q4*4) = o;
  }
  __syncthreads();
#pragma unroll
  for (int i = 0; i < 3; i++) {
    int e = tid + i * 256;
    int rl = e / 12, h = e - rl * 12;
    int m = row0 + rl;
    int b = m >> 10, s = m & 1023;
    const float* Lk = d_L + (size_t)m * NCOL + 24 + h * 2;
    float l0 = Lk[0], l1 = Lk[1];
    unsigned base = 2u * (unsigned)(m * NH + h);
    float g0 = gumbel_of_u(u_from_v23(tf_bits(0u, 1u, base)      >> 9));
    float g1 = gumbel_of_u(u_from_v23(tf_bits(0u, 1u, base + 1u) >> 9));
    int c = ((l1 + g1) > (l0 + g0)) ? 1 : 0;
    d_code[((b*NH + h) << 10) + s] = (unsigned char)c;
  }
}

// ============ attn helper ============
__device__ __forceinline__ int pick_k(unsigned long long b0, unsigned long long b1,
                                      float D0, float D1) {
  int k0 = 1023 - (int)(b0 & 1023u);
  int k1 = 1023 - (int)(b1 & 1023u);
  float s0 = D0 + gumbel_of_u(u_from_v23((unsigned)(b0 >> 10)));
  float s1 = D1 + gumbel_of_u(u_from_v23((unsigned)(b1 >> 10)));
  if (s0 > s1) return k0;
  if (s1 > s0) return k1;
  return min(k0, k1);
}

// ============ attention selection chunk (unroll 8 for ILP) ============
__global__ __launch_bounds__(256) void attn_chunk(int row0) {
  int gw = row0 + ((blockIdx.x * 256 + threadIdx.x) >> 5);
  int lane = threadIdx.x & 31;
  int bh = gw >> 10, q = gw & 1023;
  int b = bh / NH, h = bh - b*NH;

  const float* Lq = d_L + (size_t)(b*SDIM + q) * NCOL + h*2;
  float p0 = Lq[0], p1 = Lq[1];

  const unsigned char* cd = d_code + ((size_t)bh << 10);
  unsigned long long best0 = 0ull, best1 = 0ull;
  unsigned base = (unsigned)gw * 1024u;
#pragma unroll 8
  for (int k = lane; k < 1024; k += 32) {
    unsigned bits = tf_bits(0u, 2u, base + (unsigned)k);
    unsigned long long p = (((unsigned long long)(bits >> 9)) << 10) | (unsigned)(1023 - k);
    if (cd[k]) { if (p > best1) best1 = p; } else { if (p > best0) best0 = p; }
  }
#pragma unroll
  for (int o = 16; o; o >>= 1) {
    best0 = max(best0, __shfl_xor_sync(0xffffffffu, best0, o));
    best1 = max(best1, __shfl_xor_sync(0xffffffffu, best1, o));
  }
  if (lane == 0) d_kstar[gw] = pick_k(best0, best1, p0, p1);
}

// ============ 128x128 double-buffered mma.sync GEMM (M-offset) ============
__global__ __launch_bounds__(256) void mma_gemm(
    const __nv_bfloat16* __restrict__ A, const __nv_bfloat16* __restrict__ B,
    const float* __restrict__ bias, float* __restrict__ C, int Mbase)
{
  __shared__ __nv_bfloat16 As[2][128][40];
  __shared__ __nv_bfloat16 Bs[2][128][40];
  int tid = threadIdx.x;
  int wid = tid >> 5, lane = tid & 31;
  int M0 = Mbase + blockIdx.y * 128, N0 = blockIdx.x * 128;
  int wm = (wid & 1) * 64, wn = (wid >> 1) * 32;

  float acc[4][4][4] = {};
  uint4 pa[2], pb[2];
#define G_LOAD(k0) do { \
    _Pragma("unroll") \
    for (int i = 0; i < 2; i++) { \
      int ch = tid + i * 256; \
      int row = ch >> 2, c16 = (ch & 3) * 8; \
      pa[i] = *(const uint4*)(A + (size_t)(M0 + row) * KP + (k0) + c16); \
      pb[i] = *(const uint4*)(B + (size_t)(N0 + row) * KP + (k0) + c16); \
    } } while (0)
#define S_STORE(buf) do { \
    _Pragma("unroll") \
    for (int i = 0; i < 2; i++) { \
      int ch = tid + i * 256; \
      int row = ch >> 2, c16 = (ch & 3) * 8; \
      *(uint4*)&As[buf][row][c16] = pa[i]; \
      *(uint4*)&Bs[buf][row][c16] = pb[i]; \
    } } while (0)

  G_LOAD(0);
  S_STORE(0);
  __syncthreads();

  for (int c = 0; c < KCH; c++) {
    int buf = c & 1;
    if (c + 1 < KCH) G_LOAD((c + 1) * 32);
#pragma unroll
    for (int kk = 0; kk < 2; kk++) {
      int kb = kk * 16;
      uint32_t a[4][4], b[4][2];
#pragma unroll
      for (int mi = 0; mi < 4; mi++) {
        int row = wm + mi * 16 + (lane & 7) + ((lane >> 3) & 1) * 8;
        int col = kb + ((lane >> 4) << 3);
        uint32_t ad = smem_u32(&As[buf][row][col]);
        asm volatile("ldmatrix.sync.aligned.m8n8.x4.shared.b16 {%0,%1,%2,%3}, [%4];"
                     : "=r"(a[mi][0]), "=r"(a[mi][1]), "=r"(a[mi][2]), "=r"(a[mi][3])
                     : "r"(ad));
      }
#pragma unroll
      for (int ni = 0; ni < 4; ni++) {
        int nr = wn + ni * 8 + (lane & 7);
        int col = kb + (((lane >> 3) & 1) << 3);
        uint32_t bd = smem_u32(&Bs[buf][nr][col]);
        asm volatile("ldmatrix.sync.aligned.m8n8.x2.shared.b16 {%0,%1}, [%2];"
                     : "=r"(b[ni][0]), "=r"(b[ni][1]) : "r"(bd));
      }
#pragma unroll
      for (int mi = 0; mi < 4; mi++)
#pragma unroll
        for (int ni = 0; ni < 4; ni++)
          asm volatile(
              "mma.sync.aligned.m16n8k16.row.col.f32.bf16.bf16.f32 "
              "{%0,%1,%2,%3}, {%4,%5,%6,%7}, {%8,%9}, {%0,%1,%2,%3};"
              : "+f"(acc[mi][ni][0]), "+f"(acc[mi][ni][1]),
                "+f"(acc[mi][ni][2]), "+f"(acc[mi][ni][3])
              : "r"(a[mi][0]), "r"(a[mi][1]), "r"(a[mi][2]), "r"(a[mi][3]),
                "r"(b[ni][0]), "r"(b[ni][1]));
    }
    if (c + 1 < KCH) S_STORE(buf ^ 1);
    __syncthreads();
  }

  int gr = lane >> 2, gc = (lane & 3) * 2;
#pragma unroll
  for (int mi = 0; mi < 4; mi++) {
#pragma unroll
    for (int ni = 0; ni < 4; ni++) {
      int col = N0 + wn + ni * 8 + gc;
      int r0 = M0 + wm + mi * 16 + gr;
      float bx = bias[col], by = bias[col + 1];
      float2 v0 = { acc[mi][ni][0] + bx, acc[mi][ni][1] + by };
      float2 v1 = { acc[mi][ni][2] + bx, acc[mi][ni][3] + by };
      *(float2*)(C + (size_t)r0 * HDIM + col) = v0;
      *(float2*)(C + (size_t)(r0 + 8) * HDIM + col) = v1;
    }
  }
#undef G_LOAD
#undef S_STORE
}

// ============ gather chunk: V rows -> split K-folded A' ============
__global__ void gather_chunk(int mbase) {
  int t = blockIdx.x * blockDim.x + threadIdx.x;   // over M_PER_CHUNK*NH*16
  int f  = t & 15;
  int mh = t >> 4;
  int h  = mh % NH;
  int m  = mbase + mh / NH;
  int b  = m >> 10, q = m & 1023;
  int ks = d_kstar[((b*NH + h) << 10) + q];
  float4 v = *(const float4*)(d_V + (size_t)(b*SDIM + ks)*HDIM + h*HD + f*4);
  uint2 hv, lv;
  split4(v, hv, lv);
  size_t base = (size_t)m * KP + h*HD + f*4;
  *(uint2*)(d_Agp + base)        = hv;
  *(uint2*)(d_Agp + base + 768)  = hv;
  *(uint2*)(d_Agp + base + 1536) = lv;
}

extern "C" void kernel_launch(void* const* d_in, const int* in_sizes, int n_in,
                              void* d_out, int out_size) {
  // Input mapping. Primary: setup_inputs() dict order. Hedge: alphabetical.
  int iIn=0,iWq=1,ibq=2,iWk=3,ibk=4,iWv=5,ibv=6,iC=7,iWp=8,ibp=9;
  if (in_sizes[0] != MROWS*HDIM) {
    iWk=0; iWp=1; iWq=2; iWv=3; ibk=4; ibp=5; ibq=6; ibv=7; iC=8; iIn=9;
  }
  const float* x    = (const float*)d_in[iIn];
  const float* Wq   = (const float*)d_in[iWq];
  const float* bq   = (const float*)d_in[ibq];
  const float* Wk   = (const float*)d_in[iWk];
  const float* bk   = (const float*)d_in[ibk];
  const float* Wv   = (const float*)d_in[iWv];
  const float* bv   = (const float*)d_in[ibv];
  const float* cent = (const float*)d_in[iC];
  const float* Wp   = (const float*)d_in[iWp];
  const float* bp   = (const float*)d_in[ibp];
  float* out = (float*)d_out;

  float *vbuf;
  cudaGetSymbolAddress((void**)&vbuf, d_V);
  __nv_bfloat16 *ap, *agp, *bvp, *bwp;
  cudaGetSymbolAddress((void**)&ap,  d_Ap);
  cudaGetSymbolAddress((void**)&agp, d_Agp);
  cudaGetSymbolAddress((void**)&bvp, d_Bv);
  cudaGetSymbolAddress((void**)&bwp, d_Bw);

  // Side stream + events (host-side objects only; created per call — capture
  // and replays make this cost irrelevant).
  cudaStream_t s2;
  cudaEvent_t evF, evC, evL, evS[NCHUNK];
  cudaStreamCreateWithFlags(&s2, cudaStreamNonBlocking);
  cudaEventCreateWithFlags(&evF, cudaEventDisableTiming);
  cudaEventCreateWithFlags(&evC, cudaEventDisableTiming);
  cudaEventCreateWithFlags(&evL, cudaEventDisableTiming);
  for (int i = 0; i < NCHUNK; i++) cudaEventCreateWithFlags(&evS[i], cudaEventDisableTiming);

  // FORK: s2 must join the capture via an event recorded on the capturing
  // (main) stream BEFORE any launch targets s2. (R12 failed capture here.)
  cudaEventRecord(evF, 0);
  cudaStreamWaitEvent(s2, evF, 0);

  // s2: operand conversions (independent of everything)
  conv_all<<<NB_X + 2*NB_W, 256, 0, s2>>>(x, Wv, Wp);
  cudaEventRecord(evC, s2);

  // main: weight fold -> logits + centroid codes
  prep_wc<<<145, 256>>>(Wq, Wk, bq, bk, cent);
  logits_centroid<<<MROWS/64, 256>>>(x);
  cudaEventRecord(evL, 0);

  // s2: scan chunks (need logits/codes)
  cudaStreamWaitEvent(s2, evL, 0);
  for (int i = 0; i < NCHUNK; i++) {
    attn_chunk<<<ROWS_PER_CHUNK*32/256, 256, 0, s2>>>(i * ROWS_PER_CHUNK);
    cudaEventRecord(evS[i], s2);
  }

  // main: V-GEMM (needs conversions), then per-chunk gather + P-GEMM
  cudaStreamWaitEvent(0, evC, 0);
  mma_gemm<<<dim3(HDIM/128, MROWS/128), 256>>>(ap, bvp, bv, vbuf, 0);
  for (int i = 0; i < NCHUNK; i++) {
    cudaStreamWaitEvent(0, evS[i], 0);
    gather_chunk<<<M_PER_CHUNK*NH*16/256, 256>>>(i * M_PER_CHUNK);
    mma_gemm<<<dim3(HDIM/128, M_PER_CHUNK/128), 256>>>(agp, bwp, bp, out, i * M_PER_CHUNK);
  }
}

// round 14
// speedup vs baseline: 1.6442x; 1.6442x over previous
#include <cuda_runtime.h>
#include <cuda_bf16.h>
#include <cstdint>
#include <math.h>

// Problem constants
#define BDIM 8
#define SDIM 1024
#define HDIM 768
#define NH   12
#define HD   64
#define MROWS (BDIM*SDIM)        // 8192
#define NROWSEL (BDIM*NH*SDIM)   // 98304 rows (b,h,q)
#define NCOL 48                  // 24 q-logit cols | 24 k-logit cols
#define KP   2304                // split-K: [hi|hi|lo] x [hi|lo|hi]
#define KCH  72                  // KP/32 k-chunks
#define TINYF 1.17549435e-38f

// Scratch (allocation-free rule: __device__ globals)
__device__ float d_V[MROWS * HDIM];             // V = x@Wv + bv (f32)
__device__ float d_Wc[HDIM * NCOL];             // folded logit weights
__device__ float d_bc[NCOL];
__device__ float d_L[MROWS * NCOL];             // logits [8192][48] (q|k)
__device__ unsigned d_codemask[BDIM*NH*32];     // centroid codes as bitmask (bit s&31 of word [bh*32+(s>>5)])
__device__ int d_kstar[BDIM*NH*SDIM];
// split-bf16 GEMM operands (K-folded 3-product layout)
__device__ __nv_bfloat16 d_Ap[MROWS * KP];      // x:  [Ah | Ah | Al]
__device__ __nv_bfloat16 d_Agp[MROWS * KP];     // gathered V, same layout
__device__ __nv_bfloat16 d_Bv[HDIM * KP];       // WvT: [Bh | Bl | Bh]
__device__ __nv_bfloat16 d_Bw[HDIM * KP];       // WpT: [Bh | Bl | Bh]

__device__ __forceinline__ uint32_t smem_u32(const void* p) {
  uint32_t a;
  asm("{ .reg .u64 t; cvta.to.shared.u64 t, %1; cvt.u32.u64 %0, t; }" : "=r"(a) : "l"(p));
  return a;
}

// ======================= JAX threefry2x32 =======================
__device__ __forceinline__ void threefry(unsigned k0, unsigned k1,
                                         unsigned &x0, unsigned &x1) {
  unsigned k2 = k0 ^ k1 ^ 0x1BD11BDAu;
  x0 += k0; x1 += k1;
#define TF_R(r) { x0 += x1; x1 = __funnelshift_l(x1, x1, r); x1 ^= x0; }
  TF_R(13) TF_R(15) TF_R(26) TF_R(6)
  x0 += k1; x1 += k2 + 1u;
  TF_R(17) TF_R(29) TF_R(16) TF_R(24)
  x0 += k2; x1 += k0 + 2u;
  TF_R(13) TF_R(15) TF_R(26) TF_R(6)
  x0 += k0; x1 += k1 + 3u;
  TF_R(17) TF_R(29) TF_R(16) TF_R(24)
  x0 += k1; x1 += k2 + 4u;
  TF_R(13) TF_R(15) TF_R(26) TF_R(6)
  x0 += k2; x1 += k0 + 5u;
#undef TF_R
}
__device__ __forceinline__ unsigned tf_bits(unsigned k0, unsigned k1, unsigned lo) {
  unsigned x0 = 0u, x1 = lo;
  threefry(k0, k1, x0, x1);
  return x0 ^ x1;
}
__device__ __forceinline__ float u_from_v23(unsigned v23) {
  float f = __uint_as_float(v23 | 0x3f800000u) - 1.0f;
  return fmaxf(f, TINYF);
}
__device__ __forceinline__ float gumbel_of_u(float u) {
  return (float)(-log(-log((double)u)));
}

// ============ split helper ============
__device__ __forceinline__ void split4(float4 v, uint2 &h, uint2 &l) {
  unsigned short hx = __bfloat16_as_ushort(__float2bfloat16(v.x));
  unsigned short hy = __bfloat16_as_ushort(__float2bfloat16(v.y));
  unsigned short hz = __bfloat16_as_ushort(__float2bfloat16(v.z));
  unsigned short hw = __bfloat16_as_ushort(__float2bfloat16(v.w));
  unsigned short lx = __bfloat16_as_ushort(__float2bfloat16(v.x - __bfloat162float(__ushort_as_bfloat16(hx))));
  unsigned short ly = __bfloat16_as_ushort(__float2bfloat16(v.y - __bfloat162float(__ushort_as_bfloat16(hy))));
  unsigned short lz = __bfloat16_as_ushort(__float2bfloat16(v.z - __bfloat162float(__ushort_as_bfloat16(hz))));
  unsigned short lw = __bfloat16_as_ushort(__float2bfloat16(v.w - __bfloat162float(__ushort_as_bfloat16(hw))));
  h = make_uint2((unsigned)hx | ((unsigned)hy << 16), (unsigned)hz | ((unsigned)hw << 16));
  l = make_uint2((unsigned)lx | ((unsigned)ly << 16), (unsigned)lz | ((unsigned)lw << 16));
}

// ============ K1: fold Wc = [Wq@Cblk | Wk@Cblk], bc likewise ============
__global__ void prep_wc(const float* __restrict__ Wq, const float* __restrict__ Wk,
                        const float* __restrict__ bq, const float* __restrict__ bk,
                        const float* __restrict__ cent) {
  int t = blockIdx.x * blockDim.x + threadIdx.x;
  if (t < HDIM * NCOL) {
    int row = t / NCOL, j = t - row * NCOL;
    const float* W = (j < 24) ? Wq : Wk;
    int h = (j % 24) >> 1, c = j & 1;
    float s = 0.f;
#pragma unroll
    for (int d = 0; d < HD; d++)
      s += W[row * HDIM + h * HD + d] * cent[d * 2 + c];
    d_Wc[row * NCOL + j] = s;
  } else if (t < HDIM * NCOL + NCOL) {
    int j = t - HDIM * NCOL;
    const float* bb = (j < 24) ? bq : bk;
    int h = (j % 24) >> 1, c = j & 1;
    float s = 0.f;
#pragma unroll
    for (int d = 0; d < HD; d++)
      s += bb[h * HD + d] * cent[d * 2 + c];
    d_bc[j] = s;
  }
}

// ============ K2: logits+centroid-mask (blocks 0..127) || operand conversion
#define NB_LOG 128
#define NB_X   6144
#define NB_W   2304
__global__ __launch_bounds__(256) void logits_conv(
    const float* __restrict__ x,
    const float* __restrict__ Wv, const float* __restrict__ Wp)
{
  __shared__ float Xs[64][65];
  __shared__ float Ws[64][NCOL];
  __shared__ unsigned char s_code[768];   // [rl][h] codes for this 64-row block
  int tid = threadIdx.x;

  if (blockIdx.x < NB_LOG) {
    int row0 = blockIdx.x * 64;
    int r = tid & 63, g = tid >> 6;
    float acc[12] = {};
    for (int k0 = 0; k0 < HDIM; k0 += 64) {
      __syncthreads();
#pragma unroll
      for (int i = 0; i < 4; i++) {
        int f4 = tid + i * 256;
        int fr = f4 >> 4, fc = (f4 & 15) * 4;
        float4 v = *(const float4*)(x + (size_t)(row0 + fr) * HDIM + k0 + fc);
        Xs[fr][fc+0] = v.x; Xs[fr][fc+1] = v.y; Xs[fr][fc+2] = v.z; Xs[fr][fc+3] = v.w;
      }
#pragma unroll
      for (int i = 0; i < 3; i++) {
        int f4 = tid + i * 256;
        int wr = f4 / 12, wc = (f4 % 12) * 4;
        *(float4*)&Ws[wr][wc] = *(const float4*)(d_Wc + (size_t)(k0 + wr) * NCOL + wc);
      }
      __syncthreads();
#pragma unroll 4
      for (int kk = 0; kk < 64; kk++) {
        float xv = Xs[r][kk];
        const float4* w4 = (const float4*)&Ws[kk][g * 12];
#pragma unroll
        for (int q4 = 0; q4 < 3; q4++) {
          float4 w = w4[q4];
          acc[q4*4+0] += xv * w.x;
          acc[q4*4+1] += xv * w.y;
          acc[q4*4+2] += xv * w.z;
          acc[q4*4+3] += xv * w.w;
        }
      }
    }
    float* Lp = d_L + (size_t)(row0 + r) * NCOL + g * 12;
#pragma unroll
    for (int q4 = 0; q4 < 3; q4++) {
      float4 o;
      o.x = acc[q4*4+0] + d_bc[g*12 + q4*4+0];
      o.y = acc[q4*4+1] + d_bc[g*12 + q4*4+1];
      o.z = acc[q4*4+2] + d_bc[g*12 + q4*4+2];
      o.w = acc[q4*4+3] + d_bc[g*12 + q4*4+3];
      *(float4*)(Lp + q4*4) = o;
    }
    __syncthreads();
    // fused centroid selection -> smem codes (64 rows x 12 heads)
#pragma unroll
    for (int i = 0; i < 3; i++) {
      int e = tid + i * 256;
      int rl = e / 12, h = e - rl * 12;
      int m = row0 + rl;
      const float* Lk = d_L + (size_t)m * NCOL + 24 + h * 2;
      float l0 = Lk[0], l1 = Lk[1];
      unsigned base = 2u * (unsigned)(m * NH + h);
      float g0 = gumbel_of_u(u_from_v23(tf_bits(0u, 1u, base)      >> 9));
      float g1 = gumbel_of_u(u_from_v23(tf_bits(0u, 1u, base + 1u) >> 9));
      s_code[e] = (unsigned char)(((l1 + g1) > (l0 + g0)) ? 1 : 0);
    }
    __syncthreads();
    // pack to bitmask: 12 heads x 2 words (32 s each)
    if (tid < 24) {
      int h = tid >> 1, half = tid & 1;
      unsigned mword = 0;
#pragma unroll
      for (int j = 0; j < 32; j++)
        mword |= (unsigned)s_code[(half*32 + j)*12 + h] << j;
      int b = row0 >> 10, s0 = row0 & 1023;
      d_codemask[(b*NH + h)*32 + (s0 >> 5) + half] = mword;
    }
  } else if (blockIdx.x < NB_LOG + NB_X) {
    int i = (blockIdx.x - NB_LOG) * 256 + tid;
    int row = i / 192, c4 = (i - row * 192) * 4;
    uint2 h, l;
    split4(((const float4*)x)[i], h, l);
    size_t base = (size_t)row * KP + c4;
    *(uint2*)(d_Ap + base)        = h;
    *(uint2*)(d_Ap + base + 768)  = h;
    *(uint2*)(d_Ap + base + 1536) = l;
  } else {
    int wi = blockIdx.x - NB_LOG - NB_X;
    const float* W = (wi < NB_W) ? Wv : Wp;
    __nv_bfloat16* Bp = (wi < NB_W) ? d_Bv : d_Bw;
    int idx = (wi % NB_W) * 256 + tid;
    int n = idx / HDIM, k = idx - n * HDIM;
    float v = W[(size_t)k * HDIM + n];
    __nv_bfloat16 hb = __float2bfloat16(v);
    __nv_bfloat16 lb = __float2bfloat16(v - __bfloat162float(hb));
    size_t base = (size_t)n * KP;
    Bp[base + k]        = hb;
    Bp[base + 768 + k]  = lb;
    Bp[base + 1536 + k] = hb;
  }
}

// ============ attn helper ============
__device__ __forceinline__ int pick_k(unsigned long long b0, unsigned long long b1,
                                      float D0, float D1) {
  int k0 = 1023 - (int)(b0 & 1023u);
  int k1 = 1023 - (int)(b1 & 1023u);
  float s0 = D0 + gumbel_of_u(u_from_v23((unsigned)(b0 >> 10)));
  float s1 = D1 + gumbel_of_u(u_from_v23((unsigned)(b1 >> 10)));
  if (s0 > s1) return k0;
  if (s1 > s0) return k1;
  return min(k0, k1);
}

// ============ attention selection: memory-free inner loop ============
// Lane L handles contiguous k in [32L, 32L+32) -> needs only codemask word L.
// Packing (u23<<10)|(1023-k) keeps the argmax order-independent, so the lane
// remapping is semantics-preserving (ties -> smallest k, as jnp.argmax).
__global__ __launch_bounds__(256) void attn_select() {
  int gw = (blockIdx.x * 256 + threadIdx.x) >> 5;
  int lane = threadIdx.x & 31;
  if (gw >= NROWSEL) return;
  int bh = gw >> 10, q = gw & 1023;
  int b = bh / NH, h = bh - b*NH;

  const float* Lq = d_L + (size_t)(b*SDIM + q) * NCOL + h*2;
  float p0 = Lq[0], p1 = Lq[1];

  unsigned myw = d_codemask[bh*32 + lane];   // one coalesced load, then no memory
  unsigned long long best0 = 0ull, best1 = 0ull;
  unsigned base = (unsigned)gw * 1024u + (unsigned)lane * 32u;
  unsigned kk0 = 1023u - (unsigned)lane * 32u;
#pragma unroll 4
  for (int j = 0; j < 32; j++) {
    unsigned bits = tf_bits(0u, 2u, base + (unsigned)j);
    unsigned long long p = (((unsigned long long)(bits >> 9)) << 10) | (kk0 - (unsigned)j);
    if ((myw >> j) & 1u) { if (p > best1) best1 = p; } else { if (p > best0) best0 = p; }
  }
#pragma unroll
  for (int o = 16; o; o >>= 1) {
    best0 = max(best0, __shfl_xor_sync(0xffffffffu, best0, o));
    best1 = max(best1, __shfl_xor_sync(0xffffffffu, best1, o));
  }
  if (lane == 0) d_kstar[gw] = pick_k(best0, best1, p0, p1);
}

// ============ proven 128x128 double-buffered mma.sync GEMM ============
__global__ __launch_bounds__(256) void mma_gemm(
    const __nv_bfloat16* __restrict__ A, const __nv_bfloat16* __restrict__ B,
    const float* __restrict__ bias, float* __restrict__ C)
{
  __shared__ __nv_bfloat16 As[2][128][40];
  __shared__ __nv_bfloat16 Bs[2][128][40];
  int tid = threadIdx.x;
  int wid = tid >> 5, lane = tid & 31;
  int M0 = blockIdx.y * 128, N0 = blockIdx.x * 128;
  int wm = (wid & 1) * 64, wn = (wid >> 1) * 32;

  float acc[4][4][4] = {};
  uint4 pa[2], pb[2];
#define G_LOAD(k0) do { \
    _Pragma("unroll") \
    for (int i = 0; i < 2; i++) { \
      int ch = tid + i * 256; \
      int row = ch >> 2, c16 = (ch & 3) * 8; \
      pa[i] = *(const uint4*)(A + (size_t)(M0 + row) * KP + (k0) + c16); \
      pb[i] = *(const uint4*)(B + (size_t)(N0 + row) * KP + (k0) + c16); \
    } } while (0)
#define S_STORE(buf) do { \
    _Pragma("unroll") \
    for (int i = 0; i < 2; i++) { \
      int ch = tid + i * 256; \
      int row = ch >> 2, c16 = (ch & 3) * 8; \
      *(uint4*)&As[buf][row][c16] = pa[i]; \
      *(uint4*)&Bs[buf][row][c16] = pb[i]; \
    } } while (0)

  G_LOAD(0);
  S_STORE(0);
  __syncthreads();

  for (int c = 0; c < KCH; c++) {
    int buf = c & 1;
    if (c + 1 < KCH) G_LOAD((c + 1) * 32);
#pragma unroll
    for (int kk = 0; kk < 2; kk++) {
      int kb = kk * 16;
      uint32_t a[4][4], b[4][2];
#pragma unroll
      for (int mi = 0; mi < 4; mi++) {
        int row = wm + mi * 16 + (lane & 7) + ((lane >> 3) & 1) * 8;
        int col = kb + ((lane >> 4) << 3);
        uint32_t ad = smem_u32(&As[buf][row][col]);
        asm volatile("ldmatrix.sync.aligned.m8n8.x4.shared.b16 {%0,%1,%2,%3}, [%4];"
                     : "=r"(a[mi][0]), "=r"(a[mi][1]), "=r"(a[mi][2]), "=r"(a[mi][3])
                     : "r"(ad));
      }
#pragma unroll
      for (int ni = 0; ni < 4; ni++) {
        int nr = wn + ni * 8 + (lane & 7);
        int col = kb + (((lane >> 3) & 1) << 3);
        uint32_t bd = smem_u32(&Bs[buf][nr][col]);
        asm volatile("ldmatrix.sync.aligned.m8n8.x2.shared.b16 {%0,%1}, [%2];"
                     : "=r"(b[ni][0]), "=r"(b[ni][1]) : "r"(bd));
      }
#pragma unroll
      for (int mi = 0; mi < 4; mi++)
#pragma unroll
        for (int ni = 0; ni < 4; ni++)
          asm volatile(
              "mma.sync.aligned.m16n8k16.row.col.f32.bf16.bf16.f32 "
              "{%0,%1,%2,%3}, {%4,%5,%6,%7}, {%8,%9}, {%0,%1,%2,%3};"
              : "+f"(acc[mi][ni][0]), "+f"(acc[mi][ni][1]),
                "+f"(acc[mi][ni][2]), "+f"(acc[mi][ni][3])
              : "r"(a[mi][0]), "r"(a[mi][1]), "r"(a[mi][2]), "r"(a[mi][3]),
                "r"(b[ni][0]), "r"(b[ni][1]));
    }
    if (c + 1 < KCH) S_STORE(buf ^ 1);
    __syncthreads();
  }

  int gr = lane >> 2, gc = (lane & 3) * 2;
#pragma unroll
  for (int mi = 0; mi < 4; mi++) {
#pragma unroll
    for (int ni = 0; ni < 4; ni++) {
      int col = N0 + wn + ni * 8 + gc;
      int r0 = M0 + wm + mi * 16 + gr;
      float bx = bias[col], by = bias[col + 1];
      float2 v0 = { acc[mi][ni][0] + bx, acc[mi][ni][1] + by };
      float2 v1 = { acc[mi][ni][2] + bx, acc[mi][ni][3] + by };
      *(float2*)(C + (size_t)r0 * HDIM + col) = v0;
      *(float2*)(C + (size_t)(r0 + 8) * HDIM + col) = v1;
    }
  }
#undef G_LOAD
#undef S_STORE
}

// ============ gather selected V rows -> split K-folded A' ============
__global__ void gather_split() {
  int t = blockIdx.x * blockDim.x + threadIdx.x;
  if (t >= MROWS*NH*16) return;
  int f  = t & 15;
  int mh = t >> 4;
  int h  = mh % NH;
  int m  = mh / NH;
  int b  = m >> 10, q = m & 1023;
  int ks = d_kstar[((b*NH + h) << 10) + q];
  float4 v = *(const float4*)(d_V + (size_t)(b*SDIM + ks)*HDIM + h*HD + f*4);
  uint2 hv, lv;
  split4(v, hv, lv);
  size_t base = (size_t)m * KP + h*HD + f*4;
  *(uint2*)(d_Agp + base)        = hv;
  *(uint2*)(d_Agp + base + 768)  = hv;
  *(uint2*)(d_Agp + base + 1536) = lv;
}

extern "C" void kernel_launch(void* const* d_in, const int* in_sizes, int n_in,
                              void* d_out, int out_size) {
  // Input mapping. Primary: setup_inputs() dict order. Hedge: alphabetical.
  int iIn=0,iWq=1,ibq=2,iWk=3,ibk=4,iWv=5,ibv=6,iC=7,iWp=8,ibp=9;
  if (in_sizes[0] != MROWS*HDIM) {
    iWk=0; iWp=1; iWq=2; iWv=3; ibk=4; ibp=5; ibq=6; ibv=7; iC=8; iIn=9;
  }
  const float* x    = (const float*)d_in[iIn];
  const float* Wq   = (const float*)d_in[iWq];
  const float* bq   = (const float*)d_in[ibq];
  const float* Wk   = (const float*)d_in[iWk];
  const float* bk   = (const float*)d_in[ibk];
  const float* Wv   = (const float*)d_in[iWv];
  const float* bv   = (const float*)d_in[ibv];
  const float* cent = (const float*)d_in[iC];
  const float* Wp   = (const float*)d_in[iWp];
  const float* bp   = (const float*)d_in[ibp];
  float* out = (float*)d_out;

  float *vbuf;
  cudaGetSymbolAddress((void**)&vbuf, d_V);
  __nv_bfloat16 *ap, *agp, *bvp, *bwp;
  cudaGetSymbolAddress((void**)&ap,  d_Ap);
  cudaGetSymbolAddress((void**)&agp, d_Agp);
  cudaGetSymbolAddress((void**)&bvp, d_Bv);
  cudaGetSymbolAddress((void**)&bwp, d_Bw);

  // Side stream + events for fork/join inside graph capture (R11-proven).
  cudaStream_t s2;
  cudaEvent_t evF, evJ;
  cudaStreamCreateWithFlags(&s2, cudaStreamNonBlocking);
  cudaEventCreateWithFlags(&evF, cudaEventDisableTiming);
  cudaEventCreateWithFlags(&evJ, cudaEventDisableTiming);

  // K1: weight fold (feeds K2 logits)
  prep_wc<<<145, 256>>>(Wq, Wk, bq, bk, cent);

  // K2: logits+centroid mask || operand-split conversions
  logits_conv<<<NB_LOG + NB_X + 2*NB_W, 256>>>(x, Wv, Wp);

  // Fork: scan on s2, V-GEMM on main stream — hardware co-residency.
  cudaEventRecord(evF, 0);
  cudaStreamWaitEvent(s2, evF, 0);

  dim3 tg(HDIM/128, MROWS/128);
  mma_gemm<<<tg, 256>>>(ap, bvp, bv, vbuf);          // main: V = x@Wv + bv
  attn_select<<<(NROWSEL*32)/256, 256, 0, s2>>>();   // s2:  threefry scan

  // Join: main stream waits for scan before gather.
  cudaEventRecord(evJ, s2);
  cudaStreamWaitEvent(0, evJ, 0);

  // gather + P-GEMM on main stream
  gather_split<<<(MROWS*NH*16)/256, 256>>>();
  mma_gemm<<<tg, 256>>>(agp, bwp, bp, out);
}